// round 12
// baseline (speedup 1.0000x reference)
#include <cuda_runtime.h>
#include <cstdint>

#define NN 16
#define NSTEP 17
#define BMAX 131072
#define CTA_S 128
#define NT 256
#define MAXSLOT 12

// static scratch: feature-major [64][BMAX] activation buffers + dup-pair weights
__device__ float g_slot[MAXSLOT][64 * BMAX];
__device__ float g_wt[NSTEP][8192];          // [k][128]: w[o][k] duplicated pairs

struct Plan {
    int nslot;
    int encSlot, aggSlot;
    int srcSlot[NSTEP];
    int outSlot[NSTEP];
    int accum[NSTEP];
    int act[NSTEP];
    int nPreds[NSTEP];
    unsigned char predSlot[NSTEP][NN];
};

// ---------------- helpers ----------------

__device__ __forceinline__ void upk2(unsigned long long v, float& lo, float& hi) {
    unsigned a, b;
    asm("mov.b64 {%0, %1}, %2;" : "=r"(a), "=r"(b) : "l"(v));
    lo = __uint_as_float(a); hi = __uint_as_float(b);
}
__device__ __forceinline__ void ffma2(unsigned long long& acc,
                                      unsigned long long a, unsigned long long b) {
    asm("fma.rn.f32x2 %0, %1, %2, %0;" : "+l"(acc) : "l"(a), "l"(b));
}
__device__ __forceinline__ float fast_tanh(float x) {
    float e = __expf(2.f * x);
    return 1.f - __fdividef(2.f, e + 1.f);
}
// GRAPH_ACTS = [tanh, elu, softplus, sin, gaussian]
__device__ __forceinline__ float actf(int id, float v) {
    switch (id) {
        case 0:  return fast_tanh(v);
        case 1:  return v > 0.f ? v : (__expf(v) - 1.f);
        case 2:  return fmaxf(v, 0.f) + __logf(1.f + __expf(-fabsf(v)));
        case 3:  return __sinf(v);
        default: return __expf(-0.5f * v * v);
    }
}

// ---------------- weight staging: g_wt[l][k*128 + 2o (+1)] = W_l[o][k] ----------------

__global__ void wt_kernel(const float* __restrict__ W1, const float* __restrict__ gW) {
    int l = blockIdx.x;
    const float* src = (l == 0) ? W1 : gW + (l - 1) * 4096;
    float* dst = g_wt[l];
    for (int i = threadIdx.x; i < 4096; i += blockDim.x) {
        int o = i >> 6, k = i & 63;
        float w = src[i];
        dst[k * 128 + 2 * o]     = w;
        dst[k * 128 + 2 * o + 1] = w;
    }
}

// ---------------- main kernel ----------------

__global__ void __launch_bounds__(NT, 3)
inr_kernel(const float* __restrict__ inp, const float* __restrict__ lats,
           const float* __restrict__ Wl, const float* __restrict__ bl,
           const float* __restrict__ Wx, const float* __restrict__ Wy,
           const float* __restrict__ Wr, const float* __restrict__ b1,
           const float* __restrict__ gB, const float* __restrict__ outW,
           const float* __restrict__ outb, const float* __restrict__ scale,
           float* __restrict__ out, Plan pl) {
    __shared__ float s_act[64 * CTA_S];       // 32 KB: current layer's input tile
    const int t    = threadIdx.x;
    const int og   = t >> 5;                 // warp owns outputs og*8..og*8+7
    const int lane = t & 31;
    const int sb   = blockIdx.x * CTA_S;
    const int s0   = sb + lane * 4;          // this lane's 4 global samples
    const int sl4  = lane * 4;               // local sample offset

    // ---- encode -> s_act (per-sample loop to minimize live registers) ----
#pragma unroll 1
    for (int j = 0; j < 4; j++) {
        int gs = s0 + j;
        float xs = inp[gs * 3 + 0], ys = inp[gs * 3 + 1], rs = inp[gs * 3 + 2];
        const float4* lp = (const float4*)(lats + gs * 8);
        float4 l0 = lp[0], l1 = lp[1];
#pragma unroll
        for (int i = 0; i < 8; i++) {
            int o = og * 8 + i;
            const float4* wlr = (const float4*)(Wl + o * 8);
            float4 w0 = wlr[0], w1 = wlr[1];
            float pre = __ldg(bl + o);
            pre = fmaf(l0.x, w0.x, pre); pre = fmaf(l0.y, w0.y, pre);
            pre = fmaf(l0.z, w0.z, pre); pre = fmaf(l0.w, w0.w, pre);
            pre = fmaf(l1.x, w1.x, pre); pre = fmaf(l1.y, w1.y, pre);
            pre = fmaf(l1.z, w1.z, pre); pre = fmaf(l1.w, w1.w, pre);
            float lv = fast_tanh(pre);
            float xv = fast_tanh(xs * __ldg(Wx + o));
            float yv; { float z = ys * __ldg(Wy + o); yv = fmaxf(z, 0.f) + __logf(1.f + __expf(-fabsf(z))); }
            float rv; { float z = rs * __ldg(Wr + o); rv = z > 0.f ? z : (__expf(z) - 1.f); }
            float u = xv + yv + rv + lv;
            s_act[o * CTA_S + sl4 + j] = __expf(-0.5f * u * u);
        }
    }
    // NOTE: each warp wrote rows og*8..og*8+7 only; barrier below publishes all.

    // ---- 17 layers ----
    for (int st = 0; st < NSTEP; st++) {
        __syncthreads();        // st==0: encode visible; else: prev gemm done reading
                                // s_act; prev global stores visible (intra-CTA)
        if (st > 0) {
            int ss = pl.srcSlot[st];
            if (ss < 0) {       // multi-pred: sum directly into smem
                int np = pl.nPreds[st];
                const float* p0 = g_slot[pl.predSlot[st][0]] + sb;
#pragma unroll
                for (int i = 0; i < 8; i++) {
                    int q = t + i * NT;                 // 0..2047 float4 chunks
                    int off = (q >> 5) * BMAX + (q & 31) * 4;
                    float4 v = *(const float4*)(p0 + off);
                    for (int p = 1; p < np; p++) {
                        float4 u = *(const float4*)(g_slot[pl.predSlot[st][p]] + sb + off);
                        v.x += u.x; v.y += u.y; v.z += u.z; v.w += u.w;
                    }
                    *(float4*)(s_act + q * 4) = v;
                }
            } else {            // single source: bulk copy L2 -> smem
                const float* p0 = g_slot[ss] + sb;
#pragma unroll
                for (int i = 0; i < 8; i++) {
                    int q = t + i * NT;
                    int off = (q >> 5) * BMAX + (q & 31) * 4;
                    *(float4*)(s_act + q * 4) = *(const float4*)(p0 + off);
                }
            }
            __syncthreads();
        }

        // ---- GEMM: 4 samples x 8 outputs per thread; acts as sample-pairs ----
        const float* src = s_act + sl4;
        const float* wt  = g_wt[st] + og * 16;   // dup pairs for outputs og*8..+7
        unsigned long long acc[8][2];
#pragma unroll
        for (int op = 0; op < 8; op++) { acc[op][0] = 0; acc[op][1] = 0; }

#pragma unroll 8
        for (int k = 0; k < 64; k++) {
            ulonglong2 av = *(const ulonglong2*)(src + k * CTA_S);   // (s0,s1),(s2,s3)
            ulonglong2 wA = *(const ulonglong2*)(wt + k * 128);      // dup w0, w1
            ulonglong2 wB = *(const ulonglong2*)(wt + k * 128 + 4);  // dup w2, w3
            ulonglong2 wC = *(const ulonglong2*)(wt + k * 128 + 8);  // dup w4, w5
            ulonglong2 wD = *(const ulonglong2*)(wt + k * 128 + 12); // dup w6, w7
            ffma2(acc[0][0], av.x, wA.x); ffma2(acc[0][1], av.y, wA.x);
            ffma2(acc[1][0], av.x, wA.y); ffma2(acc[1][1], av.y, wA.y);
            ffma2(acc[2][0], av.x, wB.x); ffma2(acc[2][1], av.y, wB.x);
            ffma2(acc[3][0], av.x, wB.y); ffma2(acc[3][1], av.y, wB.y);
            ffma2(acc[4][0], av.x, wC.x); ffma2(acc[4][1], av.y, wC.x);
            ffma2(acc[5][0], av.x, wC.y); ffma2(acc[5][1], av.y, wC.y);
            ffma2(acc[6][0], av.x, wD.x); ffma2(acc[6][1], av.y, wD.x);
            ffma2(acc[7][0], av.x, wD.y); ffma2(acc[7][1], av.y, wD.y);
        }

        // ---- epilogue: bias + activation + store to global slot ----
        const float* bias = (st == 0) ? b1 : gB + (st - 1) * 64;
        int os = pl.outSlot[st];
        bool acm = pl.accum[st] != 0;
        int aid = pl.act[st];
        float* ob = g_slot[os];
#pragma unroll
        for (int op = 0; op < 8; op++) {
            float b = __ldg(bias + og * 8 + op);
            float v0, v1, v2, v3;
            upk2(acc[op][0], v0, v1);
            upk2(acc[op][1], v2, v3);
            float4 ve;
            ve.x = actf(aid, v0 + b); ve.y = actf(aid, v1 + b);
            ve.z = actf(aid, v2 + b); ve.w = actf(aid, v3 + b);
            float* pe = ob + (og * 8 + op) * BMAX + s0;
            if (acm) {
                float4 c = *(const float4*)pe;
                ve.x += c.x; ve.y += c.y; ve.z += c.z; ve.w += c.w;
            }
            *(float4*)pe = ve;
        }
    }
    __syncthreads();

    // ---- head: sigmoid((agg @ outW.T + outb) * scale) ----
    if (t < CTA_S) {
        int gs = sb + t;
        const float* ag = g_slot[pl.aggSlot] + gs;
        float a0 = __ldg(outb + 0), a1 = __ldg(outb + 1), a2 = __ldg(outb + 2);
#pragma unroll 8
        for (int k = 0; k < 64; k++) {
            float a = ag[(size_t)k * BMAX];
            a0 = fmaf(a, __ldg(outW + k), a0);
            a1 = fmaf(a, __ldg(outW + 64 + k), a1);
            a2 = fmaf(a, __ldg(outW + 128 + k), a2);
        }
        float sc = __ldg(scale);
        out[gs * 3 + 0] = __fdividef(1.f, 1.f + __expf(-a0 * sc));
        out[gs * 3 + 1] = __fdividef(1.f, 1.f + __expf(-a1 * sc));
        out[gs * 3 + 2] = __fdividef(1.f, 1.f + __expf(-a2 * sc));
    }
}

// ---------------- host: graph replication + slot plan ----------------

namespace {

struct MT19937 {
    uint32_t mt[624];
    int mti;
    void seed(uint32_t sd) {
        mt[0] = sd;
        for (int i = 1; i < 624; i++)
            mt[i] = 1812433253u * (mt[i-1] ^ (mt[i-1] >> 30)) + (uint32_t)i;
        mti = 624;
    }
    uint32_t next32() {
        if (mti >= 624) {
            for (int i = 0; i < 624; i++) {
                uint32_t y = (mt[i] & 0x80000000u) | (mt[(i+1)%624] & 0x7fffffffu);
                uint32_t v = mt[(i+397)%624] ^ (y >> 1);
                if (y & 1u) v ^= 0x9908b0dfu;
                mt[i] = v;
            }
            mti = 0;
        }
        uint32_t y = mt[mti++];
        y ^= y >> 11; y ^= (y << 7) & 0x9d2c5680u;
        y ^= (y << 15) & 0xefc60000u; y ^= y >> 18;
        return y;
    }
    double rnd() {
        uint32_t a = next32() >> 5, b = next32() >> 6;
        return (a * 67108864.0 + b) / 9007199254740992.0;
    }
    uint32_t randint(uint32_t n) {
        uint32_t rng = n - 1;
        if (rng == 0) return 0;
        uint32_t mask = rng;
        mask |= mask >> 1; mask |= mask >> 2; mask |= mask >> 4;
        mask |= mask >> 8; mask |= mask >> 16;
        uint32_t v;
        do { v = next32() & mask; } while (v > rng);
        return v;
    }
};

void build_plan(Plan& P) {
    MT19937 rng; rng.seed(0u);
    const int n = NN;
    bool adj[NN][NN] = {};
    for (int i = 0; i < n; i++)
        for (int d = 1; d <= 2; d++) {
            int j = (i + d) % n;
            if (rng.rnd() < 0.75) j = (int)rng.randint((uint32_t)n);
            int a = i < j ? i : j, b = i < j ? j : i;
            if (a != b) adj[a][b] = true;
        }
    unsigned pm[NN] = {};
    for (int a = 0; a < n; a++)
        for (int b = 0; b < n; b++)
            if (adj[a][b]) pm[b] |= 1u << a;
    for (int j = 1; j < n; j++)
        if (!pm[j]) {
            uint32_t a = rng.randint((uint32_t)j);
            adj[a][j] = true;
            pm[j] |= 1u << a;
        }
    bool isSink[NN];
    for (int j = 0; j < n; j++) {
        bool hs = false;
        for (int b = 0; b < n; b++) if (adj[j][b]) hs = true;
        isSink[j] = !hs;
    }

    // liveness slot allocation: values 0..15 nodes, 16 f, 17 enc
    int uses[18] = {0};
    uses[17] = 1;
    for (int j = 0; j < n; j++) {
        if (pm[j] == 0) uses[16]++;
        else for (int i = 0; i < n; i++) if ((pm[j] >> i) & 1) uses[i]++;
    }
    int freeS[24], nFree = 0, ns = 0;
    auto alloc = [&]() { return nFree ? freeS[--nFree] : ns++; };
    auto release = [&](int sl) { freeS[nFree++] = sl; };
    int slotOf[18];

    P.aggSlot = -1;
    slotOf[17] = alloc();
    P.encSlot = slotOf[17];

    P.srcSlot[0] = slotOf[17]; P.nPreds[0] = 0;
    P.act[0] = 3; P.accum[0] = 0;
    slotOf[16] = alloc();
    P.outSlot[0] = slotOf[16];
    if (--uses[17] == 0) release(slotOf[17]);

    for (int j = 0; j < n; j++) {
        int st = j + 1;
        P.act[st] = j % 5;
        P.nPreds[st] = 0;
        int np = 0;
        for (int i = 0; i < n; i++) if ((pm[j] >> i) & 1) np++;

        int srcVal = -1;
        if (np == 0) {
            srcVal = 16;
            P.srcSlot[st] = slotOf[16];
        } else if (np == 1) {
            int p = 0; while (!((pm[j] >> p) & 1)) p++;
            srcVal = p;
            P.srcSlot[st] = slotOf[p];
        } else {
            P.srcSlot[st] = -1; P.nPreds[st] = np;
            int c = 0;
            for (int i = 0; i < n; i++)
                if ((pm[j] >> i) & 1) P.predSlot[st][c++] = (unsigned char)slotOf[i];
            // preds fully consumed by the smem sum pass before the gemm writes
            for (int i = 0; i < n; i++)
                if ((pm[j] >> i) & 1) { if (--uses[i] == 0) release(slotOf[i]); }
        }

        if (isSink[j]) {
            if (P.aggSlot < 0) { P.aggSlot = alloc(); P.accum[st] = 0; }
            else P.accum[st] = 1;
            P.outSlot[st] = P.aggSlot;
        } else {
            P.accum[st] = 0;
            slotOf[j] = alloc();
            P.outSlot[st] = slotOf[j];
        }

        if (np <= 1) { if (--uses[srcVal] == 0) release(slotOf[srcVal]); }
    }
    P.nslot = ns;
}

}  // namespace

// ---------------- launch ----------------

extern "C" void kernel_launch(void* const* d_in, const int* in_sizes, int n_in,
                              void* d_out, int out_size) {
    (void)n_in; (void)out_size;
    Plan pl;
    build_plan(pl);

    const int B = in_sizes[0] / 3;
    const int ntiles = B / CTA_S;

    // stage dup-pair weights ([k][128]) for W1 + 16 graph nodes
    wt_kernel<<<NSTEP, 256>>>((const float*)d_in[7], (const float*)d_in[9]);

    inr_kernel<<<ntiles, NT>>>(
        (const float*)d_in[0],  (const float*)d_in[1],  (const float*)d_in[2],
        (const float*)d_in[3],  (const float*)d_in[4],  (const float*)d_in[5],
        (const float*)d_in[6],  (const float*)d_in[8],  (const float*)d_in[10],
        (const float*)d_in[11], (const float*)d_in[12], (const float*)d_in[13],
        (float*)d_out, pl);
}

// round 13
// speedup vs baseline: 1.6554x; 1.6554x over previous
#include <cuda_runtime.h>
#include <cstdint>

#define NN 16
#define NSTEP 17
#define BMAX 131072
#define CTA_S 128
#define NT 256
#define MAXSLOT 12

// static scratch: feature-major [64][BMAX] activation buffers + transposed weights
__device__ float g_slot[MAXSLOT][64 * BMAX];
__device__ float g_wt[NSTEP][4096];          // [k][o]

struct Plan {
    int nslot;
    int encSlot, aggSlot;
    int srcSlot[NSTEP];
    int sumSlot[NSTEP];
    int outSlot[NSTEP];
    int accum[NSTEP];
    int act[NSTEP];
    int nPreds[NSTEP];
    unsigned char predSlot[NSTEP][NN];
};

// ---------------- helpers ----------------

__device__ __forceinline__ unsigned long long pk2(float x) {
    unsigned long long r; unsigned xi = __float_as_uint(x);
    asm("mov.b64 %0, {%1, %1};" : "=l"(r) : "r"(xi));
    return r;
}
__device__ __forceinline__ void upk2(unsigned long long v, float& lo, float& hi) {
    unsigned a, b;
    asm("mov.b64 {%0, %1}, %2;" : "=r"(a), "=r"(b) : "l"(v));
    lo = __uint_as_float(a); hi = __uint_as_float(b);
}
__device__ __forceinline__ void ffma2(unsigned long long& acc,
                                      unsigned long long a, unsigned long long b) {
    asm("fma.rn.f32x2 %0, %1, %2, %0;" : "+l"(acc) : "l"(a), "l"(b));
}
__device__ __forceinline__ float fast_tanh(float x) {
    float e = __expf(2.f * x);
    return 1.f - __fdividef(2.f, e + 1.f);
}
// GRAPH_ACTS = [tanh, elu, softplus, sin, gaussian]
__device__ __forceinline__ float actf(int id, float v) {
    switch (id) {
        case 0:  return fast_tanh(v);
        case 1:  return v > 0.f ? v : (__expf(v) - 1.f);
        case 2:  return fmaxf(v, 0.f) + __logf(1.f + __expf(-fabsf(v)));
        case 3:  return __sinf(v);
        default: return __expf(-0.5f * v * v);
    }
}

// ---------------- weight transpose kernel: g_wt[l][k*64+o] = W_l[o][k] ----------------

__global__ void wt_kernel(const float* __restrict__ W1, const float* __restrict__ gW) {
    int l = blockIdx.x;
    const float* src = (l == 0) ? W1 : gW + (l - 1) * 4096;
    float* dst = g_wt[l];
    for (int i = threadIdx.x; i < 4096; i += blockDim.x) {
        int o = i >> 6, k = i & 63;
        dst[k * 64 + o] = src[i];
    }
}

// ---------------- main kernel ----------------

__global__ void __launch_bounds__(NT, 2)
inr_kernel(const float* __restrict__ inp, const float* __restrict__ lats,
           const float* __restrict__ Wl, const float* __restrict__ bl,
           const float* __restrict__ Wx, const float* __restrict__ Wy,
           const float* __restrict__ Wr, const float* __restrict__ b1,
           const float* __restrict__ gB, const float* __restrict__ outW,
           const float* __restrict__ outb, const float* __restrict__ scale,
           float* __restrict__ out, Plan pl) {
    const int t    = threadIdx.x;
    const int og   = t >> 5;                 // warp owns outputs og*8..og*8+7
    const int lane = t & 31;
    const int sb   = blockIdx.x * CTA_S;
    const int s0   = sb + lane * 4;          // this lane's 4 samples

    // ---- encode -> g_slot[encSlot] ----
    {
        float* enc = g_slot[pl.encSlot];
        float xs[4], ys[4], rs[4], lat[4][8];
#pragma unroll
        for (int j = 0; j < 4; j++) {
            int gs = s0 + j;
            xs[j] = inp[gs * 3 + 0]; ys[j] = inp[gs * 3 + 1]; rs[j] = inp[gs * 3 + 2];
            const float4* lp = (const float4*)(lats + gs * 8);
            float4 l0 = lp[0], l1 = lp[1];
            lat[j][0]=l0.x; lat[j][1]=l0.y; lat[j][2]=l0.z; lat[j][3]=l0.w;
            lat[j][4]=l1.x; lat[j][5]=l1.y; lat[j][6]=l1.z; lat[j][7]=l1.w;
        }
#pragma unroll
        for (int i = 0; i < 8; i++) {
            int o = og * 8 + i;
            const float4* wlr = (const float4*)(Wl + o * 8);
            float4 w0 = wlr[0], w1 = wlr[1];
            float blo = __ldg(bl + o), wx = __ldg(Wx + o);
            float wy = __ldg(Wy + o), wr = __ldg(Wr + o);
            float v[4];
#pragma unroll
            for (int j = 0; j < 4; j++) {
                float pre = blo;
                pre = fmaf(lat[j][0], w0.x, pre); pre = fmaf(lat[j][1], w0.y, pre);
                pre = fmaf(lat[j][2], w0.z, pre); pre = fmaf(lat[j][3], w0.w, pre);
                pre = fmaf(lat[j][4], w1.x, pre); pre = fmaf(lat[j][5], w1.y, pre);
                pre = fmaf(lat[j][6], w1.z, pre); pre = fmaf(lat[j][7], w1.w, pre);
                float lv = fast_tanh(pre);
                float xv = fast_tanh(xs[j] * wx);
                float yv; { float z = ys[j] * wy; yv = fmaxf(z, 0.f) + __logf(1.f + __expf(-fabsf(z))); }
                float rv; { float z = rs[j] * wr; rv = z > 0.f ? z : (__expf(z) - 1.f); }
                float u = xv + yv + rv + lv;
                v[j] = __expf(-0.5f * u * u);
            }
            *(float4*)(enc + o * BMAX + s0) = make_float4(v[0], v[1], v[2], v[3]);
        }
    }

    // ---- 17 layers ----
    for (int st = 0; st < NSTEP; st++) {
        __syncthreads();                       // previous layer's stores visible (same CTA)

        int ss = pl.srcSlot[st];
        if (ss < 0) {                          // multi-pred elementwise sum
            int np = pl.nPreds[st];
            float* dst = g_slot[pl.sumSlot[st]];
#pragma unroll
            for (int i = 0; i < 8; i++) {
                int off = (og * 8 + i) * BMAX + s0;
                float4 v = *(const float4*)(g_slot[pl.predSlot[st][0]] + off);
                for (int p = 1; p < np; p++) {
                    float4 u = *(const float4*)(g_slot[pl.predSlot[st][p]] + off);
                    v.x += u.x; v.y += u.y; v.z += u.z; v.w += u.w;
                }
                *(float4*)(dst + off) = v;
            }
            ss = pl.sumSlot[st];
            __syncthreads();
        }

        // ---- GEMM: warp computes outputs og*8..+7 for its lanes' 4 samples ----
        const float* src = g_slot[ss] + s0;
        const float* wt  = g_wt[st] + og * 8;   // [k][o] pairs packed (uniform LDG)
        unsigned long long acc[4][4];
#pragma unroll
        for (int op = 0; op < 4; op++)
#pragma unroll
            for (int j = 0; j < 4; j++) acc[op][j] = 0;

#pragma unroll 16
        for (int k = 0; k < 64; k++) {
            float4 av = *(const float4*)(src + (size_t)k * BMAX);
            ulonglong2 wA = *(const ulonglong2*)(wt + k * 64);       // (w0,w1),(w2,w3)
            ulonglong2 wB = *(const ulonglong2*)(wt + k * 64 + 4);   // (w4,w5),(w6,w7)
            unsigned long long a0 = pk2(av.x), a1 = pk2(av.y);
            unsigned long long a2 = pk2(av.z), a3 = pk2(av.w);
            ffma2(acc[0][0], a0, wA.x); ffma2(acc[0][1], a1, wA.x);
            ffma2(acc[0][2], a2, wA.x); ffma2(acc[0][3], a3, wA.x);
            ffma2(acc[1][0], a0, wA.y); ffma2(acc[1][1], a1, wA.y);
            ffma2(acc[1][2], a2, wA.y); ffma2(acc[1][3], a3, wA.y);
            ffma2(acc[2][0], a0, wB.x); ffma2(acc[2][1], a1, wB.x);
            ffma2(acc[2][2], a2, wB.x); ffma2(acc[2][3], a3, wB.x);
            ffma2(acc[3][0], a0, wB.y); ffma2(acc[3][1], a1, wB.y);
            ffma2(acc[3][2], a2, wB.y); ffma2(acc[3][3], a3, wB.y);
        }

        // ---- epilogue: bias + activation + store ----
        const float* bias = (st == 0) ? b1 : gB + (st - 1) * 64;
        float4 bA = *(const float4*)(bias + og * 8);
        float4 bB = *(const float4*)(bias + og * 8 + 4);
        float bb[8] = {bA.x, bA.y, bA.z, bA.w, bB.x, bB.y, bB.z, bB.w};
        int os = pl.outSlot[st];
        bool acm = pl.accum[st] != 0;
        int aid = pl.act[st];
        float* ob = g_slot[os];
#pragma unroll
        for (int op = 0; op < 4; op++) {
            float e[4], o_[4];
#pragma unroll
            for (int j = 0; j < 4; j++) upk2(acc[op][j], e[j], o_[j]);
            float4 ve, vo;
            ve.x = actf(aid, e[0] + bb[2*op]);   ve.y = actf(aid, e[1] + bb[2*op]);
            ve.z = actf(aid, e[2] + bb[2*op]);   ve.w = actf(aid, e[3] + bb[2*op]);
            vo.x = actf(aid, o_[0] + bb[2*op+1]); vo.y = actf(aid, o_[1] + bb[2*op+1]);
            vo.z = actf(aid, o_[2] + bb[2*op+1]); vo.w = actf(aid, o_[3] + bb[2*op+1]);
            float* pe = ob + (og * 8 + 2 * op) * BMAX + s0;
            float* po = pe + BMAX;
            if (acm) {
                float4 ce = *(const float4*)pe, co = *(const float4*)po;
                ve.x += ce.x; ve.y += ce.y; ve.z += ce.z; ve.w += ce.w;
                vo.x += co.x; vo.y += co.y; vo.z += co.z; vo.w += co.w;
            }
            *(float4*)pe = ve;
            *(float4*)po = vo;
        }
    }
    __syncthreads();

    // ---- head: sigmoid((agg @ outW.T + outb) * scale) ----
    if (t < CTA_S) {
        int gs = sb + t;
        const float* ag = g_slot[pl.aggSlot] + gs;
        float a0 = __ldg(outb + 0), a1 = __ldg(outb + 1), a2 = __ldg(outb + 2);
#pragma unroll 16
        for (int k = 0; k < 64; k++) {
            float a = ag[(size_t)k * BMAX];
            a0 = fmaf(a, __ldg(outW + k), a0);
            a1 = fmaf(a, __ldg(outW + 64 + k), a1);
            a2 = fmaf(a, __ldg(outW + 128 + k), a2);
        }
        float sc = __ldg(scale);
        out[gs * 3 + 0] = __fdividef(1.f, 1.f + __expf(-a0 * sc));
        out[gs * 3 + 1] = __fdividef(1.f, 1.f + __expf(-a1 * sc));
        out[gs * 3 + 2] = __fdividef(1.f, 1.f + __expf(-a2 * sc));
    }
}

// ---------------- host: graph replication + slot plan ----------------

namespace {

struct MT19937 {
    uint32_t mt[624];
    int mti;
    void seed(uint32_t sd) {
        mt[0] = sd;
        for (int i = 1; i < 624; i++)
            mt[i] = 1812433253u * (mt[i-1] ^ (mt[i-1] >> 30)) + (uint32_t)i;
        mti = 624;
    }
    uint32_t next32() {
        if (mti >= 624) {
            for (int i = 0; i < 624; i++) {
                uint32_t y = (mt[i] & 0x80000000u) | (mt[(i+1)%624] & 0x7fffffffu);
                uint32_t v = mt[(i+397)%624] ^ (y >> 1);
                if (y & 1u) v ^= 0x9908b0dfu;
                mt[i] = v;
            }
            mti = 0;
        }
        uint32_t y = mt[mti++];
        y ^= y >> 11; y ^= (y << 7) & 0x9d2c5680u;
        y ^= (y << 15) & 0xefc60000u; y ^= y >> 18;
        return y;
    }
    double rnd() {
        uint32_t a = next32() >> 5, b = next32() >> 6;
        return (a * 67108864.0 + b) / 9007199254740992.0;
    }
    uint32_t randint(uint32_t n) {
        uint32_t rng = n - 1;
        if (rng == 0) return 0;
        uint32_t mask = rng;
        mask |= mask >> 1; mask |= mask >> 2; mask |= mask >> 4;
        mask |= mask >> 8; mask |= mask >> 16;
        uint32_t v;
        do { v = next32() & mask; } while (v > rng);
        return v;
    }
};

void build_plan(Plan& P) {
    MT19937 rng; rng.seed(0u);
    const int n = NN;
    bool adj[NN][NN] = {};
    for (int i = 0; i < n; i++)
        for (int d = 1; d <= 2; d++) {
            int j = (i + d) % n;
            if (rng.rnd() < 0.75) j = (int)rng.randint((uint32_t)n);
            int a = i < j ? i : j, b = i < j ? j : i;
            if (a != b) adj[a][b] = true;
        }
    unsigned pm[NN] = {};
    for (int a = 0; a < n; a++)
        for (int b = 0; b < n; b++)
            if (adj[a][b]) pm[b] |= 1u << a;
    for (int j = 1; j < n; j++)
        if (!pm[j]) {
            uint32_t a = rng.randint((uint32_t)j);
            adj[a][j] = true;
            pm[j] |= 1u << a;
        }
    bool isSink[NN];
    for (int j = 0; j < n; j++) {
        bool hs = false;
        for (int b = 0; b < n; b++) if (adj[j][b]) hs = true;
        isSink[j] = !hs;
    }

    int uses[18] = {0};
    uses[17] = 1;
    for (int j = 0; j < n; j++) {
        if (pm[j] == 0) uses[16]++;
        else for (int i = 0; i < n; i++) if ((pm[j] >> i) & 1) uses[i]++;
    }
    int freeS[24], nFree = 0, ns = 0;
    auto alloc = [&]() { return nFree ? freeS[--nFree] : ns++; };
    auto release = [&](int sl) { freeS[nFree++] = sl; };
    int slotOf[18];

    P.aggSlot = -1;
    slotOf[17] = alloc();
    P.encSlot = slotOf[17];

    P.srcSlot[0] = slotOf[17]; P.sumSlot[0] = -1; P.nPreds[0] = 0;
    P.act[0] = 3; P.accum[0] = 0;
    slotOf[16] = alloc();
    P.outSlot[0] = slotOf[16];
    if (--uses[17] == 0) release(slotOf[17]);

    for (int j = 0; j < n; j++) {
        int st = j + 1;
        P.act[st] = j % 5;
        P.sumSlot[st] = -1; P.nPreds[st] = 0;
        int np = 0;
        for (int i = 0; i < n; i++) if ((pm[j] >> i) & 1) np++;

        int srcVal = -1;
        if (np == 0) {
            srcVal = 16;
            P.srcSlot[st] = slotOf[16];
        } else if (np == 1) {
            int p = 0; while (!((pm[j] >> p) & 1)) p++;
            srcVal = p;
            P.srcSlot[st] = slotOf[p];
        } else {
            P.srcSlot[st] = -1; P.nPreds[st] = np;
            int c = 0;
            for (int i = 0; i < n; i++)
                if ((pm[j] >> i) & 1) P.predSlot[st][c++] = (unsigned char)slotOf[i];
            for (int i = 0; i < n; i++)
                if ((pm[j] >> i) & 1) { if (--uses[i] == 0) release(slotOf[i]); }
            P.sumSlot[st] = alloc();
        }

        if (isSink[j]) {
            if (P.aggSlot < 0) { P.aggSlot = alloc(); P.accum[st] = 0; }
            else P.accum[st] = 1;
            P.outSlot[st] = P.aggSlot;
        } else {
            P.accum[st] = 0;
            slotOf[j] = alloc();
            P.outSlot[st] = slotOf[j];
        }

        if (np > 1) release(P.sumSlot[st]);
        else if (--uses[srcVal] == 0) release(slotOf[srcVal]);
    }
    P.nslot = ns;
}

}  // namespace

// ---------------- launch ----------------

extern "C" void kernel_launch(void* const* d_in, const int* in_sizes, int n_in,
                              void* d_out, int out_size) {
    (void)n_in; (void)out_size;
    Plan pl;
    build_plan(pl);

    const int B = in_sizes[0] / 3;
    const int ntiles = B / CTA_S;

    // stage transposed weights ([k][o]) for W1 + 16 graph nodes
    wt_kernel<<<NSTEP, 256>>>((const float*)d_in[7], (const float*)d_in[9]);

    inr_kernel<<<ntiles, NT>>>(
        (const float*)d_in[0],  (const float*)d_in[1],  (const float*)d_in[2],
        (const float*)d_in[3],  (const float*)d_in[4],  (const float*)d_in[5],
        (const float*)d_in[6],  (const float*)d_in[8],  (const float*)d_in[10],
        (const float*)d_in[11], (const float*)d_in[12], (const float*)d_in[13],
        (float*)d_out, pl);
}